// round 2
// baseline (speedup 1.0000x reference)
#include <cuda_runtime.h>
#include <math.h>

// Problem constants (fixed by the reference)
#define B_SZ 65536
#define IN2  256
#define H2   512
#define G3   1536   // 3*H2
#define NQ   64     // two heads of 32, packed

#define ACT_NONE 0
#define ACT_RELU 1

// Scratch (allocation-free rule: __device__ globals)
__device__ float g_x  [(size_t)B_SZ * H2];   // fc1 output      (134 MB)
__device__ float g_gi [(size_t)B_SZ * G3];   // x @ W_ih^T + b  (403 MB)
__device__ float g_gh [(size_t)B_SZ * G3];   // h @ W_hh^T + b  (403 MB)
__device__ float g_wcat[NQ * H2];            // concat(W21, W22)
__device__ float g_bcat[NQ];

// ---------------------------------------------------------------------------
// Generic tiled GEMM:  C[M,N] = act(A[M,K] @ W[N,K]^T + bias[N])
// BM=128, BN=64, BK=32, 256 threads, 8x4 per-thread micro-tile.
// M % 128 == 0, N % 64 == 0, K % 32 == 0 (all shapes here satisfy this).
// ---------------------------------------------------------------------------
template <int ACT>
__global__ __launch_bounds__(256, 2) void gemm_bias_kernel(
    const float* __restrict__ A, const float* __restrict__ W,
    const float* __restrict__ bias, float* __restrict__ C,
    int K, int N)
{
    __shared__ __align__(16) float As[32][132];  // [k][m], padded for banks/alignment
    __shared__ __align__(16) float Ws[32][68];   // [k][n]

    const int bm  = blockIdx.y * 128;
    const int bn  = blockIdx.x * 64;
    const int tid = threadIdx.x;
    const int tx  = tid & 15;   // -> 4 output cols
    const int ty  = tid >> 4;   // -> 8 output rows

    float acc[8][4];
#pragma unroll
    for (int i = 0; i < 8; i++)
#pragma unroll
        for (int j = 0; j < 4; j++) acc[i][j] = 0.0f;

    for (int k0 = 0; k0 < K; k0 += 32) {
        // Load A tile: 128 rows x 32 cols = 1024 float4, 4 per thread (coalesced)
#pragma unroll
        for (int it = 0; it < 4; it++) {
            int id = tid + it * 256;
            int r  = id >> 3;
            int c  = (id & 7) << 2;
            const float4 v = *(const float4*)(A + (size_t)(bm + r) * K + k0 + c);
            As[c + 0][r] = v.x; As[c + 1][r] = v.y;
            As[c + 2][r] = v.z; As[c + 3][r] = v.w;
        }
        // Load W tile: 64 rows x 32 cols = 512 float4, 2 per thread (coalesced)
#pragma unroll
        for (int it = 0; it < 2; it++) {
            int id = tid + it * 256;
            int r  = id >> 3;
            int c  = (id & 7) << 2;
            const float4 v = *(const float4*)(W + (size_t)(bn + r) * K + k0 + c);
            Ws[c + 0][r] = v.x; Ws[c + 1][r] = v.y;
            Ws[c + 2][r] = v.z; Ws[c + 3][r] = v.w;
        }
        __syncthreads();

#pragma unroll
        for (int k = 0; k < 32; k++) {
            const float4 a0 = *(const float4*)&As[k][ty * 8];
            const float4 a1 = *(const float4*)&As[k][ty * 8 + 4];
            const float4 wv = *(const float4*)&Ws[k][tx * 4];
            const float a[8] = {a0.x, a0.y, a0.z, a0.w, a1.x, a1.y, a1.z, a1.w};
            const float w[4] = {wv.x, wv.y, wv.z, wv.w};
#pragma unroll
            for (int i = 0; i < 8; i++)
#pragma unroll
                for (int j = 0; j < 4; j++)
                    acc[i][j] = fmaf(a[i], w[j], acc[i][j]);
        }
        __syncthreads();
    }

    const float4 bv = *(const float4*)(bias + bn + tx * 4);
#pragma unroll
    for (int i = 0; i < 8; i++) {
        float4 o;
        o.x = acc[i][0] + bv.x;
        o.y = acc[i][1] + bv.y;
        o.z = acc[i][2] + bv.z;
        o.w = acc[i][3] + bv.w;
        if (ACT == ACT_RELU) {
            o.x = fmaxf(o.x, 0.0f); o.y = fmaxf(o.y, 0.0f);
            o.z = fmaxf(o.z, 0.0f); o.w = fmaxf(o.w, 0.0f);
        }
        *(float4*)(C + (size_t)(bm + ty * 8 + i) * N + bn + tx * 4) = o;
    }
}

// ---------------------------------------------------------------------------
// GRU gate epilogue (PyTorch GRUCell semantics):
//   r = sigmoid(i_r + h_r); z = sigmoid(i_z + h_z)
//   n = tanh(i_n + r * h_n); h' = (1-z)*n + z*h
// ---------------------------------------------------------------------------
__device__ __forceinline__ float sigmoidf_(float x) {
    return 1.0f / (1.0f + __expf(-x));
}

__global__ __launch_bounds__(256) void gru_gates_kernel(
    const float* __restrict__ gi, const float* __restrict__ gh,
    const float* __restrict__ h_in, float* __restrict__ h_out)
{
    const int idx = blockIdx.x * blockDim.x + threadIdx.x;   // over B*H2/4
    const int row = idx / (H2 / 4);
    const int jc  = (idx % (H2 / 4)) * 4;
    const size_t base = (size_t)row * G3 + jc;

    const float4 ir = *(const float4*)(gi + base);
    const float4 iz = *(const float4*)(gi + base + H2);
    const float4 in4 = *(const float4*)(gi + base + 2 * H2);
    const float4 hr = *(const float4*)(gh + base);
    const float4 hz = *(const float4*)(gh + base + H2);
    const float4 hn = *(const float4*)(gh + base + 2 * H2);
    const float4 hv = *(const float4*)(h_in + (size_t)row * H2 + jc);

    float4 o;
    {
        float r = sigmoidf_(ir.x + hr.x);
        float z = sigmoidf_(iz.x + hz.x);
        float n = tanhf(in4.x + r * hn.x);
        o.x = (1.0f - z) * n + z * hv.x;
    }
    {
        float r = sigmoidf_(ir.y + hr.y);
        float z = sigmoidf_(iz.y + hz.y);
        float n = tanhf(in4.y + r * hn.y);
        o.y = (1.0f - z) * n + z * hv.y;
    }
    {
        float r = sigmoidf_(ir.z + hr.z);
        float z = sigmoidf_(iz.z + hz.z);
        float n = tanhf(in4.z + r * hn.z);
        o.z = (1.0f - z) * n + z * hv.z;
    }
    {
        float r = sigmoidf_(ir.w + hr.w);
        float z = sigmoidf_(iz.w + hz.w);
        float n = tanhf(in4.w + r * hn.w);
        o.w = (1.0f - z) * n + z * hv.w;
    }
    *(float4*)(h_out + (size_t)row * H2 + jc) = o;
}

// ---------------------------------------------------------------------------
// Pack concat(W21, W22) / concat(b21, b22). Row j<32 -> W21[j], else W22[j-32].
// With this packing, q_interleaved[(2b+s)*32+a] == (h @ Wcat^T)[b, s*32+a],
// i.e. the [B,64] GEMM output IS the interleaved q, flattened row-major.
// ---------------------------------------------------------------------------
__global__ void pack_heads_kernel(const float* __restrict__ W21,
                                  const float* __restrict__ b21,
                                  const float* __restrict__ W22,
                                  const float* __restrict__ b22)
{
    const int i = blockIdx.x * blockDim.x + threadIdx.x;
    if (i < NQ * H2) {
        const int r = i / H2;
        const int c = i % H2;
        g_wcat[i] = (r < 32) ? W21[r * H2 + c] : W22[(r - 32) * H2 + c];
    }
    if (i < NQ) {
        g_bcat[i] = (i < 32) ? b21[i] : b22[i - 32];
    }
}

// ---------------------------------------------------------------------------
// kernel_launch
// ---------------------------------------------------------------------------
extern "C" void kernel_launch(void* const* d_in, const int* in_sizes, int n_in,
                              void* d_out, int out_size)
{
    const float* inputs = (const float*)d_in[0];
    const float* hidden = (const float*)d_in[1];
    const float* W1     = (const float*)d_in[2];
    const float* b1     = (const float*)d_in[3];
    const float* W_ih   = (const float*)d_in[4];
    const float* W_hh   = (const float*)d_in[5];
    const float* b_ih   = (const float*)d_in[6];
    const float* b_hh   = (const float*)d_in[7];
    const float* W21    = (const float*)d_in[8];
    const float* b21    = (const float*)d_in[9];
    const float* W22    = (const float*)d_in[10];
    const float* b22    = (const float*)d_in[11];

    float* out_q = (float*)d_out;                       // [2B, 32] interleaved
    float* out_h = out_q + (size_t)2 * B_SZ * 32;       // [B, H2]

    float *gx, *ggi, *ggh, *gw, *gb;
    cudaGetSymbolAddress((void**)&gx,  g_x);
    cudaGetSymbolAddress((void**)&ggi, g_gi);
    cudaGetSymbolAddress((void**)&ggh, g_gh);
    cudaGetSymbolAddress((void**)&gw,  g_wcat);
    cudaGetSymbolAddress((void**)&gb,  g_bcat);

    // Pack head weights (independent of GEMMs below, tiny)
    pack_heads_kernel<<<(NQ * H2 + 255) / 256, 256>>>(W21, b21, W22, b22);

    // fc1: x = relu(inputs @ W1^T + b1)    [B, IN2] -> [B, H2]
    gemm_bias_kernel<ACT_RELU><<<dim3(H2 / 64, B_SZ / 128), 256>>>(
        inputs, W1, b1, gx, IN2, H2);

    // gi = x @ W_ih^T + b_ih               [B, H2] -> [B, 3*H2]
    gemm_bias_kernel<ACT_NONE><<<dim3(G3 / 64, B_SZ / 128), 256>>>(
        gx, W_ih, b_ih, ggi, H2, G3);

    // gh = hidden @ W_hh^T + b_hh          [B, H2] -> [B, 3*H2]
    gemm_bias_kernel<ACT_NONE><<<dim3(G3 / 64, B_SZ / 128), 256>>>(
        hidden, W_hh, b_hh, ggh, H2, G3);

    // gates -> h' (written straight into the output buffer)
    gru_gates_kernel<<<(B_SZ * H2 / 4) / 256, 256>>>(ggi, ggh, hidden, out_h);

    // q heads: out_q = h' @ Wcat^T + bcat  [B, H2] -> [B, 64] (== interleaved q)
    gemm_bias_kernel<ACT_NONE><<<dim3(NQ / 64, B_SZ / 128), 256>>>(
        out_h, gw, gb, out_q, H2, NQ);
}

// round 8
// speedup vs baseline: 4.2499x; 4.2499x over previous
#include <cuda_runtime.h>
#include <cuda_fp16.h>
#include <cstdint>
#include <math.h>

// Problem constants
#define B_SZ 65536
#define IN2  256
#define H2   512
#define G3   1536
#define NQ   64

#define ACT_NONE 0
#define ACT_RELU 1

// ---------------------------------------------------------------------------
// Scratch (__device__ globals; allocation-free rule)
// ---------------------------------------------------------------------------
__device__ __half g_in_h [(size_t)B_SZ * IN2];   // inputs fp16
__device__ __half g_hid_h[(size_t)B_SZ * H2];    // hidden fp16
__device__ __half g_x_h  [(size_t)B_SZ * H2];    // fc1 out fp16
__device__ __half g_hp_h [(size_t)B_SZ * H2];    // h' fp16 (for head GEMM)
__device__ float  g_gi   [(size_t)B_SZ * G3];
__device__ float  g_gh   [(size_t)B_SZ * G3];
__device__ __half g_W1h  [H2 * IN2];
__device__ __half g_Wih_h[G3 * H2];
__device__ __half g_Whh_h[G3 * H2];
__device__ __half g_wcat_h[NQ * H2];
__device__ float  g_bcat [NQ];

// ---------------------------------------------------------------------------
// fp32 -> fp16 conversion (vectorized, n must be multiple of 4)
// ---------------------------------------------------------------------------
__global__ void f2h_kernel(const float* __restrict__ src,
                           __half* __restrict__ dst, int n4)
{
    int i = blockIdx.x * blockDim.x + threadIdx.x;
    if (i < n4) {
        float4 v = ((const float4*)src)[i];
        ((__half2*)dst)[2 * i]     = __floats2half2_rn(v.x, v.y);
        ((__half2*)dst)[2 * i + 1] = __floats2half2_rn(v.z, v.w);
    }
}

// Pack concat(W21,W22) to fp16 + concat(b21,b22) fp32.
__global__ void pack_heads_kernel(const float* __restrict__ W21,
                                  const float* __restrict__ b21,
                                  const float* __restrict__ W22,
                                  const float* __restrict__ b22)
{
    const int i = blockIdx.x * blockDim.x + threadIdx.x;
    if (i < NQ * H2) {
        const int r = i / H2;
        const int c = i % H2;
        float v = (r < 32) ? W21[r * H2 + c] : W22[(r - 32) * H2 + c];
        g_wcat_h[i] = __float2half_rn(v);
    }
    if (i < NQ)
        g_bcat[i] = (i < 32) ? b21[i] : b22[i - 32];
}

// ---------------------------------------------------------------------------
// Tensor-core GEMM: C[M,N] = act(A[M,K] @ W[N,K]^T + bias[N])
// fp16 inputs, fp32 accum. mma.sync.m16n8k16. 256 threads = 8 warps.
// Warp tile 64x32. Block tile: BM = WM*64, BN = WN*32, BK = 32.
// Fragment loads are plain 32-bit LDS (A row-major & W[N,K] row-major both
// have k contiguous, matching the .row / .col fragment layouts).
// LDK=40 halves padding -> compute-phase LDS is bank-conflict-free.
// ---------------------------------------------------------------------------
template <int WM, int WN, int ACT, bool OUT_HALF>
__global__ __launch_bounds__(256, 2) void hgemm_kernel(
    const __half* __restrict__ A, const __half* __restrict__ W,
    const float* __restrict__ bias, void* __restrict__ Cout,
    int M, int N, int K)
{
    constexpr int BM = WM * 64;
    constexpr int BN = WN * 32;
    constexpr int BK = 32;
    constexpr int LDK = 40;

    __shared__ __align__(16) __half As[BM][LDK];
    __shared__ __align__(16) __half Bs[BN][LDK];

    const int tid  = threadIdx.x;
    const int warp = tid >> 5, lane = tid & 31;
    const int g = lane >> 2, t = lane & 3;
    const int wm = warp / WN, wn = warp % WN;
    const int bm = blockIdx.y * BM, bn = blockIdx.x * BN;
    const int row0 = wm * 64, col0 = wn * 32;

    float acc[4][4][4];
#pragma unroll
    for (int i = 0; i < 4; i++)
#pragma unroll
        for (int j = 0; j < 4; j++)
#pragma unroll
            for (int q = 0; q < 4; q++) acc[i][j][q] = 0.0f;

    for (int k0 = 0; k0 < K; k0 += BK) {
        // A tile: BM x 32 halves; uint4 = 8 halves; BM*4 chunks over 256 thr
#pragma unroll
        for (int it = 0; it < BM / 64; ++it) {
            int idx = tid + it * 256;
            int r = idx >> 2, c = (idx & 3) * 8;
            *(uint4*)&As[r][c] =
                *(const uint4*)(A + (size_t)(bm + r) * K + k0 + c);
        }
        // W tile: BN x 32 halves
#pragma unroll
        for (int it = 0; it < BN / 64; ++it) {
            int idx = tid + it * 256;
            int r = idx >> 2, c = (idx & 3) * 8;
            *(uint4*)&Bs[r][c] =
                *(const uint4*)(W + (size_t)(bn + r) * K + k0 + c);
        }
        __syncthreads();

#pragma unroll
        for (int kf = 0; kf < 2; ++kf) {
            const int kb = kf * 16;
            uint32_t a[4][4], b[4][2];
#pragma unroll
            for (int i = 0; i < 4; i++) {
                int r = row0 + i * 16 + g;
                a[i][0] = *(const uint32_t*)&As[r][kb + 2 * t];
                a[i][1] = *(const uint32_t*)&As[r + 8][kb + 2 * t];
                a[i][2] = *(const uint32_t*)&As[r][kb + 2 * t + 8];
                a[i][3] = *(const uint32_t*)&As[r + 8][kb + 2 * t + 8];
            }
#pragma unroll
            for (int j = 0; j < 4; j++) {
                int c = col0 + j * 8 + g;
                b[j][0] = *(const uint32_t*)&Bs[c][kb + 2 * t];
                b[j][1] = *(const uint32_t*)&Bs[c][kb + 2 * t + 8];
            }
#pragma unroll
            for (int i = 0; i < 4; i++)
#pragma unroll
                for (int j = 0; j < 4; j++)
                    asm volatile(
                        "mma.sync.aligned.m16n8k16.row.col.f32.f16.f16.f32 "
                        "{%0,%1,%2,%3}, {%4,%5,%6,%7}, {%8,%9}, {%0,%1,%2,%3};"
                        : "+f"(acc[i][j][0]), "+f"(acc[i][j][1]),
                          "+f"(acc[i][j][2]), "+f"(acc[i][j][3])
                        : "r"(a[i][0]), "r"(a[i][1]), "r"(a[i][2]), "r"(a[i][3]),
                          "r"(b[j][0]), "r"(b[j][1]));
        }
        __syncthreads();
    }

    // Epilogue: acc[i][j]: {row g, cols 2t,2t+1} and {row g+8, cols 2t,2t+1}
#pragma unroll
    for (int i = 0; i < 4; i++) {
#pragma unroll
        for (int j = 0; j < 4; j++) {
            const int c = bn + col0 + j * 8 + 2 * t;
            const float bx = bias[c], by = bias[c + 1];
            float v0 = acc[i][j][0] + bx, v1 = acc[i][j][1] + by;
            float v2 = acc[i][j][2] + bx, v3 = acc[i][j][3] + by;
            if (ACT == ACT_RELU) {
                v0 = fmaxf(v0, 0.f); v1 = fmaxf(v1, 0.f);
                v2 = fmaxf(v2, 0.f); v3 = fmaxf(v3, 0.f);
            }
            const int r0 = bm + row0 + i * 16 + g;
            if (OUT_HALF) {
                __half2* C = (__half2*)Cout;
                C[((size_t)r0 * N + c) >> 1]       = __floats2half2_rn(v0, v1);
                C[((size_t)(r0 + 8) * N + c) >> 1] = __floats2half2_rn(v2, v3);
            } else {
                float* C = (float*)Cout;
                float2 o0 = {v0, v1}, o1 = {v2, v3};
                *(float2*)&C[(size_t)r0 * N + c]       = o0;
                *(float2*)&C[(size_t)(r0 + 8) * N + c] = o1;
            }
        }
    }
}

// ---------------------------------------------------------------------------
// GRU gate epilogue; writes fp32 h' to output and fp16 copy for head GEMM.
// ---------------------------------------------------------------------------
__device__ __forceinline__ float sigmoidf_(float x) {
    return 1.0f / (1.0f + __expf(-x));
}

__global__ __launch_bounds__(256) void gru_gates_kernel(
    const float* __restrict__ gi, const float* __restrict__ gh,
    const float* __restrict__ h_in, float* __restrict__ h_out,
    __half* __restrict__ h_out_h)
{
    const int idx = blockIdx.x * blockDim.x + threadIdx.x;
    const int row = idx / (H2 / 4);
    const int jc  = (idx % (H2 / 4)) * 4;
    const size_t base = (size_t)row * G3 + jc;

    const float4 ir  = *(const float4*)(gi + base);
    const float4 iz  = *(const float4*)(gi + base + H2);
    const float4 in4 = *(const float4*)(gi + base + 2 * H2);
    const float4 hr  = *(const float4*)(gh + base);
    const float4 hz  = *(const float4*)(gh + base + H2);
    const float4 hn  = *(const float4*)(gh + base + 2 * H2);
    const float4 hv  = *(const float4*)(h_in + (size_t)row * H2 + jc);

    float4 o;
    {
        float r = sigmoidf_(ir.x + hr.x);
        float z = sigmoidf_(iz.x + hz.x);
        float n = tanhf(in4.x + r * hn.x);
        o.x = (1.0f - z) * n + z * hv.x;
    }
    {
        float r = sigmoidf_(ir.y + hr.y);
        float z = sigmoidf_(iz.y + hz.y);
        float n = tanhf(in4.y + r * hn.y);
        o.y = (1.0f - z) * n + z * hv.y;
    }
    {
        float r = sigmoidf_(ir.z + hr.z);
        float z = sigmoidf_(iz.z + hz.z);
        float n = tanhf(in4.z + r * hn.z);
        o.z = (1.0f - z) * n + z * hv.z;
    }
    {
        float r = sigmoidf_(ir.w + hr.w);
        float z = sigmoidf_(iz.w + hz.w);
        float n = tanhf(in4.w + r * hn.w);
        o.w = (1.0f - z) * n + z * hv.w;
    }
    *(float4*)(h_out + (size_t)row * H2 + jc) = o;

    __half2* hh = (__half2*)(h_out_h + (size_t)row * H2 + jc);
    hh[0] = __floats2half2_rn(o.x, o.y);
    hh[1] = __floats2half2_rn(o.z, o.w);
}

// ---------------------------------------------------------------------------
// kernel_launch
// ---------------------------------------------------------------------------
extern "C" void kernel_launch(void* const* d_in, const int* in_sizes, int n_in,
                              void* d_out, int out_size)
{
    const float* inputs = (const float*)d_in[0];
    const float* hidden = (const float*)d_in[1];
    const float* W1     = (const float*)d_in[2];
    const float* b1     = (const float*)d_in[3];
    const float* W_ih   = (const float*)d_in[4];
    const float* W_hh   = (const float*)d_in[5];
    const float* b_ih   = (const float*)d_in[6];
    const float* b_hh   = (const float*)d_in[7];
    const float* W21    = (const float*)d_in[8];
    const float* b21    = (const float*)d_in[9];
    const float* W22    = (const float*)d_in[10];
    const float* b22    = (const float*)d_in[11];

    float* out_q = (float*)d_out;                   // [2B, 32] interleaved
    float* out_h = out_q + (size_t)2 * B_SZ * 32;   // [B, H2]

    __half *inh, *hidh, *xh, *hph, *w1h, *wihh, *whhh, *wcath;
    float *ggi, *ggh, *bcat;
    cudaGetSymbolAddress((void**)&inh,  g_in_h);
    cudaGetSymbolAddress((void**)&hidh, g_hid_h);
    cudaGetSymbolAddress((void**)&xh,   g_x_h);
    cudaGetSymbolAddress((void**)&hph,  g_hp_h);
    cudaGetSymbolAddress((void**)&ggi,  g_gi);
    cudaGetSymbolAddress((void**)&ggh,  g_gh);
    cudaGetSymbolAddress((void**)&w1h,  g_W1h);
    cudaGetSymbolAddress((void**)&wihh, g_Wih_h);
    cudaGetSymbolAddress((void**)&whhh, g_Whh_h);
    cudaGetSymbolAddress((void**)&wcath, g_wcat_h);
    cudaGetSymbolAddress((void**)&bcat, g_bcat);

    // fp32 -> fp16 conversions
    f2h_kernel<<<(B_SZ * IN2 / 4 + 255) / 256, 256>>>(inputs, inh, B_SZ * IN2 / 4);
    f2h_kernel<<<(B_SZ * H2 / 4 + 255) / 256, 256>>>(hidden, hidh, B_SZ * H2 / 4);
    f2h_kernel<<<(H2 * IN2 / 4 + 255) / 256, 256>>>(W1, w1h, H2 * IN2 / 4);
    f2h_kernel<<<(G3 * H2 / 4 + 255) / 256, 256>>>(W_ih, wihh, G3 * H2 / 4);
    f2h_kernel<<<(G3 * H2 / 4 + 255) / 256, 256>>>(W_hh, whhh, G3 * H2 / 4);
    pack_heads_kernel<<<(NQ * H2 + 255) / 256, 256>>>(W21, b21, W22, b22);

    // fc1: x = relu(inputs @ W1^T + b1), fp16 out
    hgemm_kernel<2, 4, ACT_RELU, true><<<dim3(H2 / 128, B_SZ / 128), 256>>>(
        inh, w1h, b1, xh, B_SZ, H2, IN2);

    // gi = x @ W_ih^T + b_ih  (fp32 out)
    hgemm_kernel<2, 4, ACT_NONE, false><<<dim3(G3 / 128, B_SZ / 128), 256>>>(
        xh, wihh, b_ih, ggi, B_SZ, G3, H2);

    // gh = hidden @ W_hh^T + b_hh  (fp32 out)
    hgemm_kernel<2, 4, ACT_NONE, false><<<dim3(G3 / 128, B_SZ / 128), 256>>>(
        hidh, whhh, b_hh, ggh, B_SZ, G3, H2);

    // gates -> h' (fp32 to output, fp16 copy for heads)
    gru_gates_kernel<<<(B_SZ * H2 / 4) / 256, 256>>>(ggi, ggh, hidden, out_h, hph);

    // q heads: out_q = h' @ Wcat^T + bcat  [B,64] == interleaved q
    hgemm_kernel<4, 2, ACT_NONE, false><<<dim3(NQ / 64, B_SZ / 256), 256>>>(
        hph, wcath, bcat, out_q, B_SZ, NQ, H2);
}